// round 11
// baseline (speedup 1.0000x reference)
#include <cuda_runtime.h>
#include <cuda_bf16.h>
#include <math.h>

#define B      32
#define TA     512
#define TT     128
#define HH     512
#define GG     1536
#define D2     1024
#define NMFCC  80
#define NEMB   300
#define AUD_T  513
#define NCLS   7

// ---- device scratch ----
// gi and GRU outputs are TIME-MAJOR, BATCH-INTERLEAVED: row index = t*B + b.
__device__ float g_x_text[B*TT*NEMB];
__device__ float g_gi_a[2u*B*TA*GG];
__device__ float g_gi_t[2u*B*TT*GG];
__device__ float g_out_a0[B*TA*D2];
__device__ float g_out_a1[B*TA*D2];
__device__ float g_out_t0[B*TT*D2];
__device__ float g_out_t1[B*TT*D2];
__device__ float g_H1[B*1088];
__device__ float g_H2[B*1088];
// staged h: per group, double-buffered; word = tf32bits (top 19) | tag8 (low bits)
#define STG_GRP (2*B*HH)
__device__ unsigned g_stage[8*STG_GRP];

__device__ __forceinline__ unsigned tf32c(float x) {
    unsigned u; asm("cvt.rna.tf32.f32 %0, %1;" : "=r"(u) : "f"(x)); return u;
}
__device__ __forceinline__ float fast_tanh(float x) {
    float y; asm("tanh.approx.f32 %0, %1;" : "=f"(y) : "f"(x)); return y;
}
__device__ __forceinline__ void mma_tf32(float* c, const unsigned* a, const unsigned* b) {
    asm("mma.sync.aligned.m16n8k8.row.col.f32.tf32.tf32.f32 "
        "{%0,%1,%2,%3},{%4,%5,%6,%7},{%8,%9},{%0,%1,%2,%3};"
        : "+f"(c[0]), "+f"(c[1]), "+f"(c[2]), "+f"(c[3])
        : "r"(a[0]), "r"(a[1]), "r"(a[2]), "r"(a[3]), "r"(b[0]), "r"(b[1]));
}
__device__ __forceinline__ uint4 ldcg4(const unsigned* p) {
    uint4 v;
    asm volatile("ld.global.cg.v4.u32 {%0,%1,%2,%3}, [%4];"
                 : "=r"(v.x), "=r"(v.y), "=r"(v.z), "=r"(v.w) : "l"(p) : "memory");
    return v;
}
__device__ __forceinline__ void stcg(unsigned* p, unsigned v) {
    asm volatile("st.global.cg.u32 [%0], %1;" :: "l"(p), "r"(v) : "memory");
}

// fused: staging clear (removes stale tags across graph replays) + text embedding
__global__ void init_kernel(const int* __restrict__ itext, const float* __restrict__ emb) {
    int i = blockIdx.x * blockDim.x + threadIdx.x;
    if (i < 8*STG_GRP) g_stage[i] = 0u;
    if (i < B*TT*NEMB) {
        int e = i % NEMB, bt = i / NEMB;
        g_x_text[i] = emb[(long long)itext[bt] * NEMB + e];
    }
}

// ---- fused tf32 tensor-core GEMM: 4 jobs in one launch ----
struct GJob { const float* X; const float* W; const float* bias; float* C;
              int K; int rows_per_b; long long bstride; long long xrstride; };
struct GJobs { GJob j[4]; int yoff[5]; };

__global__ __launch_bounds__(256) void tgemm(GJobs js)
{
    __shared__ unsigned Xs[32][136];
    __shared__ unsigned Ws[32][136];
    const int tid = threadIdx.x;
    const int lane = tid & 31, wid = tid >> 5;
    const int warpM = wid & 3, warpN = wid >> 2;
    const int lr = lane >> 2, lc = lane & 3;

    int jj = 0;
#pragma unroll
    for (int q = 1; q < 4; q++) if ((int)blockIdx.y >= js.yoff[q]) jj = q;
    const GJob jb = js.j[jj];
    const int K = jb.K;
    const int m_base = (blockIdx.y - js.yoff[jj]) * 128;
    const int n_base = blockIdx.x * 128;

    float acc[2][8][4];
#pragma unroll
    for (int mt = 0; mt < 2; mt++)
#pragma unroll
        for (int nt = 0; nt < 8; nt++)
#pragma unroll
            for (int q = 0; q < 4; q++) acc[mt][nt][q] = 0.f;

    const int row = tid >> 1;
    const int f4b = (tid & 1) * 4;
    const int mg = m_base + row;
    const int bb = mg / jb.rows_per_b, rr = mg - bb * jb.rows_per_b;
    const float* xrow = jb.X + (long long)bb * jb.bstride + (long long)rr * jb.xrstride;
    const float* wrow = jb.W + (long long)(n_base + row) * K;

    for (int k0 = 0; k0 < K; k0 += 32) {
#pragma unroll
        for (int q = 0; q < 4; q++) {
            int ks = (f4b + q) * 4;
            int kk = k0 + ks;
            float4 xv = make_float4(0.f,0.f,0.f,0.f), wv = xv;
            if (kk + 4 <= K) { xv = *(const float4*)(xrow + kk); wv = *(const float4*)(wrow + kk); }
            Xs[ks+0][row]=tf32c(xv.x); Xs[ks+1][row]=tf32c(xv.y);
            Xs[ks+2][row]=tf32c(xv.z); Xs[ks+3][row]=tf32c(xv.w);
            Ws[ks+0][row]=tf32c(wv.x); Ws[ks+1][row]=tf32c(wv.y);
            Ws[ks+2][row]=tf32c(wv.z); Ws[ks+3][row]=tf32c(wv.w);
        }
        __syncthreads();
#pragma unroll
        for (int kk = 0; kk < 4; kk++) {
            const int kb = kk * 8;
            unsigned a[2][4], b[8][2];
#pragma unroll
            for (int mt = 0; mt < 2; mt++) {
                int mr = warpM*32 + mt*16;
                a[mt][0] = Xs[kb+lc][mr + lr];
                a[mt][1] = Xs[kb+lc][mr + 8 + lr];
                a[mt][2] = Xs[kb+4+lc][mr + lr];
                a[mt][3] = Xs[kb+4+lc][mr + 8 + lr];
            }
#pragma unroll
            for (int nt = 0; nt < 8; nt++) {
                int nc = warpN*64 + nt*8;
                b[nt][0] = Ws[kb+lc][nc + lr];
                b[nt][1] = Ws[kb+4+lc][nc + lr];
            }
#pragma unroll
            for (int mt = 0; mt < 2; mt++)
#pragma unroll
                for (int nt = 0; nt < 8; nt++) mma_tf32(acc[mt][nt], a[mt], b[nt]);
        }
        __syncthreads();
    }
#pragma unroll
    for (int mt = 0; mt < 2; mt++) {
#pragma unroll
        for (int half = 0; half < 2; half++) {
            int mr = m_base + warpM*32 + mt*16 + lr + half*8;
            int bbo = mr / jb.rows_per_b, rro = mr - bbo * jb.rows_per_b;
            long long crow = (long long)rro * 32 + bbo;    // interleaved row t*32+b
#pragma unroll
            for (int nt = 0; nt < 8; nt++) {
                int nc = n_base + warpN*64 + nt*8 + 2*lc;
                float2 v;
                v.x = acc[mt][nt][half*2+0] + jb.bias[nc];
                v.y = acc[mt][nt][half*2+1] + jb.bias[nc+1];
                *(float2*)(jb.C + crow * GG + nc) = v;
            }
        }
    }
}

// ---- persistent tf32 GRU scan: 4 groups x 32 CTAs, CTA owns 16 h-cols ----
// 12 warps: warp = (m in {r,z,n}, kq in 0..3).
// h exchange is SELF-VALIDATING with FULL tf32 precision: staged word =
// tf32bits (low 13 bits are zero by cvt.rna) | tag8 in the low bits.
// The data load IS the sync — no flags, no fences, no separate polls.
struct ScanJob { const float* gi; const float* whh; const float* bhh; float* out;
                 int T; int dir; int dOff; int ctr; };
struct ScanArgs { ScanJob job[4]; };

#define HSW 516
#define RB  33
#define SCAN_SMEM ((32*HSW + 4*48*RB) * 4)
#define TF32MASK 0xffffe000u

__global__ __launch_bounds__(384, 1) void scan_kernel(ScanArgs args)
{
    const int group = blockIdx.x >> 5, c = blockIdx.x & 31;
    const ScanJob jb = args.job[group];
    unsigned* stg = g_stage + jb.ctr * STG_GRP;

    extern __shared__ unsigned smu[];
    unsigned* hbits = smu;                       // 32 x 516 (tf32 h)
    float* red = (float*)(smu + 32*HSW);         // 4 x 48 x 33
    __shared__ float bhh_s[48];

    const int tid  = threadIdx.x;
    const int lane = tid & 31, wid = tid >> 5;
    const int m = wid % 3, kq = wid / 3;         // gate tile, k-quarter
    const int lr = lane >> 2, lc = lane & 3;

    if (tid < 48) {
        int gl = tid;
        int grow = (gl < 16) ? (c*16 + gl) : (gl < 32) ? (512 + c*16 + gl - 16) : (1024 + c*16 + gl - 32);
        bhh_s[gl] = jb.bhh[grow];
    }
    __syncthreads();

    // preload Whh fragments (static for whole scan)
    unsigned aF[16][4];
    {
        const int r0 = m*512 + c*16 + lr;
        const int r1 = r0 + 8;
#pragma unroll
        for (int ks = 0; ks < 16; ks++) {
            int kg = kq*128 + ks*8 + lc;
            aF[ks][0] = tf32c(__ldg(jb.whh + r0*512 + kg));
            aF[ks][1] = tf32c(__ldg(jb.whh + r1*512 + kg));
            aF[ks][2] = tf32c(__ldg(jb.whh + r0*512 + kg + 4));
            aF[ks][3] = tf32c(__ldg(jb.whh + r1*512 + kg + 4));
        }
    }

    // finalize mapping (coalesced): item = b*16 + col
    const int col0 = tid & 15,          b0i = tid >> 4;           // items 0..383
    const int col1 = (tid + 384) & 15,  b1i = (tid + 384) >> 4;   // items 384..511
    const bool has1 = (tid < 128);
    float hp0 = 0.f, hp1 = 0.f;

    for (int s = 0; s < jb.T; s++) {
        const int t = jb.dir ? (jb.T - 1 - s) : s;

        // gi prefetch — h-independent, overlaps the staged-h spin
        long long gb0 = ((long long)(t*32 + b0i))*GG + c*16 + col0;
        float giR0 = __ldg(jb.gi + gb0);
        float giZ0 = __ldg(jb.gi + gb0 + 512);
        float giN0 = __ldg(jb.gi + gb0 + 1024);
        float giR1 = 0.f, giZ1 = 0.f, giN1 = 0.f;
        if (has1) {
            long long gb1 = ((long long)(t*32 + b1i))*GG + c*16 + col1;
            giR1 = __ldg(jb.gi + gb1);
            giZ1 = __ldg(jb.gi + gb1 + 512);
            giN1 = __ldg(jb.gi + gb1 + 1024);
        }

        if (s == 0) {
            for (int b = m; b < 32; b += 3)
                *(uint4*)&hbits[b*HSW + kq*128 + lane*4] = make_uint4(0u,0u,0u,0u);
        } else {
            // self-validating load of this quarter: spin until all tags match
            const unsigned tag = ((unsigned)(s - 1) & 127u) + 1u;   // producer step s-1
            const unsigned* src = stg + ((s-1)&1)*(B*HH) + kq*128;
            for (int b = m; b < 32; b += 3) {
                const unsigned* p = src + b*512 + lane*4;
                uint4 v = ldcg4(p);
                while ((((v.x ^ tag) | (v.y ^ tag) | (v.z ^ tag) | (v.w ^ tag)) & 0xffu) != 0u)
                    v = ldcg4(p);
                v.x &= TF32MASK; v.y &= TF32MASK;
                v.z &= TF32MASK; v.w &= TF32MASK;
                *(uint4*)&hbits[b*HSW + kq*128 + lane*4] = v;
            }
        }
        // triple barrier: the 3 warps of quarter kq (96 threads)
        asm volatile("bar.sync %0, %1;" :: "r"(kq + 1), "r"(96) : "memory");

        // tensor GEMM: C[48 x 32] partial over this warp's k-quarter
        float acc[4][4];
#pragma unroll
        for (int nt = 0; nt < 4; nt++)
#pragma unroll
            for (int q = 0; q < 4; q++) acc[nt][q] = 0.f;
#pragma unroll
        for (int ks = 0; ks < 16; ks++) {
            const int kg = kq*128 + ks*8;
#pragma unroll
            for (int nt = 0; nt < 4; nt++) {
                unsigned bfr[2];
                bfr[0] = hbits[(nt*8 + lr)*HSW + kg + lc];
                bfr[1] = hbits[(nt*8 + lr)*HSW + kg + lc + 4];
                mma_tf32(acc[nt], aF[ks], bfr);
            }
        }
        {
            float* rp = red + kq*48*RB;
#pragma unroll
            for (int nt = 0; nt < 4; nt++) {
                int gr = m*16 + lr, bc = nt*8 + 2*lc;
                rp[gr*RB + bc]       = acc[nt][0];
                rp[gr*RB + bc + 1]   = acc[nt][1];
                rp[(gr+8)*RB + bc]   = acc[nt][2];
                rp[(gr+8)*RB + bc+1] = acc[nt][3];
            }
        }
        __syncthreads();   // also: all 32 producers' step-(s-1) data observed by this
                           // CTA before any step-s staging store (WAR safe, double buffer)

        // finalize gates; stage tagged tf32 h (critical path), defer fp32 out[]
        unsigned* dstS = stg + (s&1)*(B*HH);
        const unsigned tagN = ((unsigned)s & 127u) + 1u;   // tag for step s
        float hn0, hn1 = 0.f;
        {
            float gr=0, gz=0, gn=0;
#pragma unroll
            for (int q = 0; q < 4; q++) {
                const float* rp = red + q*48*RB;
                gr += rp[col0*RB + b0i];
                gz += rp[(16+col0)*RB + b0i];
                gn += rp[(32+col0)*RB + b0i];
            }
            float r = 1.f/(1.f + __expf(-(giR0 + gr + bhh_s[col0])));
            float z = 1.f/(1.f + __expf(-(giZ0 + gz + bhh_s[16+col0])));
            float n = fast_tanh(giN0 + r*(gn + bhh_s[32+col0]));
            hn0 = (1.f - z)*n + z*hp0;
            hp0 = hn0;
            stcg(dstS + b0i*512 + c*16 + col0, tf32c(hn0) | tagN);
        }
        if (has1) {
            float gr=0, gz=0, gn=0;
#pragma unroll
            for (int q = 0; q < 4; q++) {
                const float* rp = red + q*48*RB;
                gr += rp[col1*RB + b1i];
                gz += rp[(16+col1)*RB + b1i];
                gn += rp[(32+col1)*RB + b1i];
            }
            float r = 1.f/(1.f + __expf(-(giR1 + gr + bhh_s[col1])));
            float z = 1.f/(1.f + __expf(-(giZ1 + gz + bhh_s[16+col1])));
            float n = fast_tanh(giN1 + r*(gn + bhh_s[32+col1]));
            hn1 = (1.f - z)*n + z*hp1;
            hp1 = hn1;
            stcg(dstS + b1i*512 + c*16 + col1, tf32c(hn1) | tagN);
        }

        // off-critical-path fp32 outputs
        jb.out[((long long)(t*32 + b0i))*D2 + jb.dOff + c*16 + col0] = hn0;
        if (has1)
            jb.out[((long long)(t*32 + b1i))*D2 + jb.dOff + c*16 + col1] = hn1;
    }
}

// ---- attention (seq rows interleaved: row = t*B + b) ----
__global__ __launch_bounds__(256) void attn_kernel(
    const float* __restrict__ lastbuf, int lastt,
    const float* __restrict__ seqbuf, int T,
    const float* __restrict__ i_audio, int mode, float* __restrict__ Hout)
{
    __shared__ float alast[1024];
    __shared__ float sc[512];
    __shared__ float pros_s[64];
    __shared__ float p2s;
    __shared__ float redsm[8];
    const int b = blockIdx.x, tid = threadIdx.x;
    const int w = tid >> 5, lane = tid & 31;

    for (int d = tid; d < 1024; d += 256)
        alast[d] = lastbuf[((long long)(lastt*B + b))*D2 + d];
    if (tid < 64) pros_s[tid] = i_audio[((long long)(b*AUD_T + TA))*NMFCC + tid];
    __syncthreads();
    if (tid < 32) {
        float v = 0.f;
        for (int j = tid; j < 64; j += 32) v += pros_s[j]*pros_s[j];
#pragma unroll
        for (int o = 16; o; o >>= 1) v += __shfl_down_sync(0xffffffffu, v, o);
        if (tid == 0) p2s = v;
    }
    __syncthreads();
    for (int t = w; t < T; t += 8) {
        const float* row = seqbuf + ((long long)(t*B + b))*D2;
        float v = 0.f;
        for (int d = lane; d < 1024; d += 32) v += alast[d] * row[d];
#pragma unroll
        for (int o = 16; o; o >>= 1) v += __shfl_down_sync(0xffffffffu, v, o);
        if (lane == 0) sc[t] = v + p2s;
    }
    __syncthreads();
    float ps = 0.f;
    for (int t = tid; t < T; t += 256) ps += sc[t];
#pragma unroll
    for (int o = 16; o; o >>= 1) ps += __shfl_down_sync(0xffffffffu, ps, o);
    if (lane == 0) redsm[w] = ps;
    __syncthreads();
    if (tid == 0) { float S=0.f; for (int i=0;i<8;i++) S += redsm[i]; redsm[0]=S; }
    __syncthreads();
    float S = redsm[0];
    float denom = (mode == 1) ? S : (1.f + S);
    float sumA  = (mode == 1) ? 1.f : ((float)T + S) / denom;
    __syncthreads();
    for (int t = tid; t < T; t += 256)
        sc[t] = ((mode == 1) ? sc[t] : (1.f + sc[t])) / denom;
    __syncthreads();
    float acc[4] = {0.f,0.f,0.f,0.f};
    for (int t = 0; t < T; t++) {
        float a = sc[t];
        const float* row = seqbuf + ((long long)(t*B + b))*D2;
#pragma unroll
        for (int q = 0; q < 4; q++) acc[q] += a * row[tid + q*256];
    }
#pragma unroll
    for (int q = 0; q < 4; q++) Hout[b*1088 + tid + q*256] = acc[q];
    if (tid < 64) Hout[b*1088 + 1024 + tid] = sumA * pros_s[tid];
}

__global__ void final_kernel(const float* __restrict__ fc_w, const float* __restrict__ fc_b,
                             const float* __restrict__ H1, const float* __restrict__ H2,
                             float* __restrict__ out)
{
    const int b = blockIdx.x;
    const int w = threadIdx.x >> 5, lane = threadIdx.x & 31;
    __shared__ float lg[NCLS];
    if (w < NCLS) {
        const float* wr = fc_w + w * 2176;
        float acc = 0.f;
        for (int i = lane; i < 1088; i += 32) acc += H1[b*1088 + i] * wr[i];
        for (int i = lane; i < 1088; i += 32) acc += H2[b*1088 + i] * wr[1088 + i];
#pragma unroll
        for (int o = 16; o; o >>= 1) acc += __shfl_down_sync(0xffffffffu, acc, o);
        if (lane == 0) lg[w] = acc + fc_b[w];
    }
    __syncthreads();
    if (threadIdx.x == 0) {
        float m = lg[0];
        for (int c = 1; c < NCLS; c++) m = fmaxf(m, lg[c]);
        float e[NCLS], s = 0.f;
        for (int c = 0; c < NCLS; c++) { e[c] = expf(lg[c] - m); s += e[c]; }
        for (int c = 0; c < NCLS; c++) out[b*NCLS + c] = e[c] / s;
    }
}

extern "C" void kernel_launch(void* const* d_in, const int* in_sizes, int n_in,
                              void* d_out, int out_size)
{
    const float* i_audio = (const float*)d_in[0];
    const int*   i_text  = (const int*)  d_in[1];
    const float* emb     = (const float*)d_in[2];
    const float* fc_w    = (const float*)d_in[3];
    const float* fc_b    = (const float*)d_in[4];
    const float* aWih0   = (const float*)d_in[5];
    const float* aWhh0   = (const float*)d_in[6];
    const float* ab0     = (const float*)d_in[7];
    const float* aWih1   = (const float*)d_in[8];
    const float* aWhh1   = (const float*)d_in[9];
    const float* ab1     = (const float*)d_in[10];
    const float* tWih0   = (const float*)d_in[11];
    const float* tWhh0   = (const float*)d_in[12];
    const float* tb0     = (const float*)d_in[13];
    const float* tWih1   = (const float*)d_in[14];
    const float* tWhh1   = (const float*)d_in[15];
    const float* tb1     = (const float*)d_in[16];
    float* out = (float*)d_out;

    float *gi_a, *gi_t, *xt, *oa0, *oa1, *ot0, *ot1, *h1, *h2;
    cudaGetSymbolAddress((void**)&gi_a, g_gi_a);
    cudaGetSymbolAddress((void**)&gi_t, g_gi_t);
    cudaGetSymbolAddress((void**)&xt,   g_x_text);
    cudaGetSymbolAddress((void**)&oa0,  g_out_a0);
    cudaGetSymbolAddress((void**)&oa1,  g_out_a1);
    cudaGetSymbolAddress((void**)&ot0,  g_out_t0);
    cudaGetSymbolAddress((void**)&ot1,  g_out_t1);
    cudaGetSymbolAddress((void**)&h1,   g_H1);
    cudaGetSymbolAddress((void**)&h2,   g_H2);

    cudaFuncSetAttribute(scan_kernel, cudaFuncAttributeMaxDynamicSharedMemorySize, SCAN_SMEM);

    const long long SLA = (long long)B*TA*GG;
    const long long SLT = (long long)B*TT*GG;
    const int WHH = GG*HH;

    init_kernel<<<(B*TT*NEMB + 255)/256, 256>>>(i_text, emb);

    GJobs g0;
    g0.j[0] = { i_audio, aWih0,          ab0,      gi_a,     NMFCC, TA, (long long)AUD_T*NMFCC, NMFCC };
    g0.j[1] = { i_audio, aWih0+GG*NMFCC, ab0+2*GG, gi_a+SLA, NMFCC, TA, (long long)AUD_T*NMFCC, NMFCC };
    g0.j[2] = { xt,      tWih0,          tb0,      gi_t,     NEMB,  TT, (long long)TT*NEMB,    NEMB };
    g0.j[3] = { xt,      tWih0+GG*NEMB,  tb0+2*GG, gi_t+SLT, NEMB,  TT, (long long)TT*NEMB,    NEMB };
    g0.yoff[0]=0; g0.yoff[1]=128; g0.yoff[2]=256; g0.yoff[3]=288; g0.yoff[4]=320;
    tgemm<<<dim3(GG/128, 320), 256>>>(g0);

    ScanArgs s0;
    s0.job[0] = { gi_a,     aWhh0,     ab0+GG,   oa0, TA, 0, 0,   0 };
    s0.job[1] = { gi_a+SLA, aWhh0+WHH, ab0+3*GG, oa0, TA, 1, 512, 1 };
    s0.job[2] = { gi_t,     tWhh0,     tb0+GG,   ot0, TT, 0, 0,   2 };
    s0.job[3] = { gi_t+SLT, tWhh0+WHH, tb0+3*GG, ot0, TT, 1, 512, 3 };
    scan_kernel<<<128, 384, SCAN_SMEM>>>(s0);

    GJobs g1;
    g1.j[0] = { oa0, aWih1,       ab1,      gi_a,     D2, TA, (long long)D2, (long long)B*D2 };
    g1.j[1] = { oa0, aWih1+GG*D2, ab1+2*GG, gi_a+SLA, D2, TA, (long long)D2, (long long)B*D2 };
    g1.j[2] = { ot0, tWih1,       tb1,      gi_t,     D2, TT, (long long)D2, (long long)B*D2 };
    g1.j[3] = { ot0, tWih1+GG*D2, tb1+2*GG, gi_t+SLT, D2, TT, (long long)D2, (long long)B*D2 };
    g1.yoff[0]=0; g1.yoff[1]=128; g1.yoff[2]=256; g1.yoff[3]=288; g1.yoff[4]=320;
    tgemm<<<dim3(GG/128, 320), 256>>>(g1);

    ScanArgs s1;
    s1.job[0] = { gi_a,     aWhh1,     ab1+GG,   oa1, TA, 0, 0,   4 };
    s1.job[1] = { gi_a+SLA, aWhh1+WHH, ab1+3*GG, oa1, TA, 1, 512, 5 };
    s1.job[2] = { gi_t,     tWhh1,     tb1+GG,   ot1, TT, 0, 0,   6 };
    s1.job[3] = { gi_t+SLT, tWhh1+WHH, tb1+3*GG, ot1, TT, 1, 512, 7 };
    scan_kernel<<<128, 384, SCAN_SMEM>>>(s1);

    attn_kernel<<<B, 256>>>(oa1, TA-1, ot1, TT, i_audio, 1, h1);
    attn_kernel<<<B, 256>>>(ot1, TT-1, oa1, TA, i_audio, 2, h2);
    final_kernel<<<B, 256>>>(fc_w, fc_b, h1, h2, out);
}

// round 12
// speedup vs baseline: 1.3274x; 1.3274x over previous
#include <cuda_runtime.h>
#include <cuda_bf16.h>
#include <math.h>

#define B      32
#define TA     512
#define TT     128
#define HH     512
#define GG     1536
#define D2     1024
#define NMFCC  80
#define NEMB   300
#define AUD_T  513
#define NCLS   7

// ---- device scratch ----
// gi and GRU outputs are TIME-MAJOR, BATCH-INTERLEAVED: row index = t*B + b.
__device__ float g_x_text[B*TT*NEMB];
__device__ float g_gi_a[2u*B*TA*GG];
__device__ float g_gi_t[2u*B*TT*GG];
__device__ float g_out_a0[B*TA*D2];
__device__ float g_out_a1[B*TA*D2];
__device__ float g_out_t0[B*TT*D2];
__device__ float g_out_t1[B*TT*D2];
__device__ float g_H1[B*1088];
__device__ float g_H2[B*1088];
// staged h: per group, double-buffered; word = tf32bits (top 19) | tag8 (low bits)
#define STG_GRP (2*B*HH)
__device__ unsigned g_stage[8*STG_GRP];

__device__ __forceinline__ unsigned tf32c(float x) {
    unsigned u; asm("cvt.rna.tf32.f32 %0, %1;" : "=r"(u) : "f"(x)); return u;
}
__device__ __forceinline__ float fast_tanh(float x) {
    float y; asm("tanh.approx.f32 %0, %1;" : "=f"(y) : "f"(x)); return y;
}
__device__ __forceinline__ void mma_tf32(float* c, const unsigned* a, const unsigned* b) {
    asm("mma.sync.aligned.m16n8k8.row.col.f32.tf32.tf32.f32 "
        "{%0,%1,%2,%3},{%4,%5,%6,%7},{%8,%9},{%0,%1,%2,%3};"
        : "+f"(c[0]), "+f"(c[1]), "+f"(c[2]), "+f"(c[3])
        : "r"(a[0]), "r"(a[1]), "r"(a[2]), "r"(a[3]), "r"(b[0]), "r"(b[1]));
}
__device__ __forceinline__ uint4 ldcg4(const unsigned* p) {
    uint4 v;
    asm volatile("ld.global.cg.v4.u32 {%0,%1,%2,%3}, [%4];"
                 : "=r"(v.x), "=r"(v.y), "=r"(v.z), "=r"(v.w) : "l"(p) : "memory");
    return v;
}
__device__ __forceinline__ void stcg(unsigned* p, unsigned v) {
    asm volatile("st.global.cg.u32 [%0], %1;" :: "l"(p), "r"(v) : "memory");
}

// fused: staging clear (removes stale tags across graph replays) + text embedding
__global__ void init_kernel(const int* __restrict__ itext, const float* __restrict__ emb) {
    int i = blockIdx.x * blockDim.x + threadIdx.x;
    if (i < 8*STG_GRP) g_stage[i] = 0u;
    if (i < B*TT*NEMB) {
        int e = i % NEMB, bt = i / NEMB;
        g_x_text[i] = emb[(long long)itext[bt] * NEMB + e];
    }
}

// ---- fused tf32 tensor-core GEMM: 4 jobs in one launch ----
struct GJob { const float* X; const float* W; const float* bias; float* C;
              int K; int rows_per_b; long long bstride; long long xrstride; };
struct GJobs { GJob j[4]; int yoff[5]; };

__global__ __launch_bounds__(256) void tgemm(GJobs js)
{
    __shared__ unsigned Xs[32][136];
    __shared__ unsigned Ws[32][136];
    const int tid = threadIdx.x;
    const int lane = tid & 31, wid = tid >> 5;
    const int warpM = wid & 3, warpN = wid >> 2;
    const int lr = lane >> 2, lc = lane & 3;

    int jj = 0;
#pragma unroll
    for (int q = 1; q < 4; q++) if ((int)blockIdx.y >= js.yoff[q]) jj = q;
    const GJob jb = js.j[jj];
    const int K = jb.K;
    const int m_base = (blockIdx.y - js.yoff[jj]) * 128;
    const int n_base = blockIdx.x * 128;

    float acc[2][8][4];
#pragma unroll
    for (int mt = 0; mt < 2; mt++)
#pragma unroll
        for (int nt = 0; nt < 8; nt++)
#pragma unroll
            for (int q = 0; q < 4; q++) acc[mt][nt][q] = 0.f;

    const int row = tid >> 1;
    const int f4b = (tid & 1) * 4;
    const int mg = m_base + row;
    const int bb = mg / jb.rows_per_b, rr = mg - bb * jb.rows_per_b;
    const float* xrow = jb.X + (long long)bb * jb.bstride + (long long)rr * jb.xrstride;
    const float* wrow = jb.W + (long long)(n_base + row) * K;

    for (int k0 = 0; k0 < K; k0 += 32) {
#pragma unroll
        for (int q = 0; q < 4; q++) {
            int ks = (f4b + q) * 4;
            int kk = k0 + ks;
            float4 xv = make_float4(0.f,0.f,0.f,0.f), wv = xv;
            if (kk + 4 <= K) { xv = *(const float4*)(xrow + kk); wv = *(const float4*)(wrow + kk); }
            Xs[ks+0][row]=tf32c(xv.x); Xs[ks+1][row]=tf32c(xv.y);
            Xs[ks+2][row]=tf32c(xv.z); Xs[ks+3][row]=tf32c(xv.w);
            Ws[ks+0][row]=tf32c(wv.x); Ws[ks+1][row]=tf32c(wv.y);
            Ws[ks+2][row]=tf32c(wv.z); Ws[ks+3][row]=tf32c(wv.w);
        }
        __syncthreads();
#pragma unroll
        for (int kk = 0; kk < 4; kk++) {
            const int kb = kk * 8;
            unsigned a[2][4], b[8][2];
#pragma unroll
            for (int mt = 0; mt < 2; mt++) {
                int mr = warpM*32 + mt*16;
                a[mt][0] = Xs[kb+lc][mr + lr];
                a[mt][1] = Xs[kb+lc][mr + 8 + lr];
                a[mt][2] = Xs[kb+4+lc][mr + lr];
                a[mt][3] = Xs[kb+4+lc][mr + 8 + lr];
            }
#pragma unroll
            for (int nt = 0; nt < 8; nt++) {
                int nc = warpN*64 + nt*8;
                b[nt][0] = Ws[kb+lc][nc + lr];
                b[nt][1] = Ws[kb+4+lc][nc + lr];
            }
#pragma unroll
            for (int mt = 0; mt < 2; mt++)
#pragma unroll
                for (int nt = 0; nt < 8; nt++) mma_tf32(acc[mt][nt], a[mt], b[nt]);
        }
        __syncthreads();
    }
#pragma unroll
    for (int mt = 0; mt < 2; mt++) {
#pragma unroll
        for (int half = 0; half < 2; half++) {
            int mr = m_base + warpM*32 + mt*16 + lr + half*8;
            int bbo = mr / jb.rows_per_b, rro = mr - bbo * jb.rows_per_b;
            long long crow = (long long)rro * 32 + bbo;    // interleaved row t*32+b
#pragma unroll
            for (int nt = 0; nt < 8; nt++) {
                int nc = n_base + warpN*64 + nt*8 + 2*lc;
                float2 v;
                v.x = acc[mt][nt][half*2+0] + jb.bias[nc];
                v.y = acc[mt][nt][half*2+1] + jb.bias[nc+1];
                *(float2*)(jb.C + crow * GG + nc) = v;
            }
        }
    }
}

// ---- persistent tf32 GRU scan: 4 groups x 32 CTAs, CTA owns 16 h-cols ----
// 12 warps: warp = (m in {r,z,n}, kq in 0..3).
// h exchange: SELF-VALIDATING tagged words (tf32bits | tag8) with a
// TWO-PHASE load: issue all loads (MLP), then verify tags / retry stragglers.
// Two full __syncthreads per step (pre- and post-finalize) protect red/hbits.
struct ScanJob { const float* gi; const float* whh; const float* bhh; float* out;
                 int T; int dir; int dOff; int ctr; };
struct ScanArgs { ScanJob job[4]; };

#define HSW 516
#define RB  33
#define SCAN_SMEM ((32*HSW + 4*48*RB) * 4)
#define TF32MASK 0xffffe000u

__global__ __launch_bounds__(384, 1) void scan_kernel(ScanArgs args)
{
    const int group = blockIdx.x >> 5, c = blockIdx.x & 31;
    const ScanJob jb = args.job[group];
    unsigned* stg = g_stage + jb.ctr * STG_GRP;

    extern __shared__ unsigned smu[];
    unsigned* hbits = smu;                       // 32 x 516 (tf32 h)
    float* red = (float*)(smu + 32*HSW);         // 4 x 48 x 33
    __shared__ float bhh_s[48];

    const int tid  = threadIdx.x;
    const int lane = tid & 31, wid = tid >> 5;
    const int m = wid % 3, kq = wid / 3;         // gate tile, k-quarter
    const int lr = lane >> 2, lc = lane & 3;

    if (tid < 48) {
        int gl = tid;
        int grow = (gl < 16) ? (c*16 + gl) : (gl < 32) ? (512 + c*16 + gl - 16) : (1024 + c*16 + gl - 32);
        bhh_s[gl] = jb.bhh[grow];
    }
    __syncthreads();

    // preload Whh fragments (static for whole scan)
    unsigned aF[16][4];
    {
        const int r0 = m*512 + c*16 + lr;
        const int r1 = r0 + 8;
#pragma unroll
        for (int ks = 0; ks < 16; ks++) {
            int kg = kq*128 + ks*8 + lc;
            aF[ks][0] = tf32c(__ldg(jb.whh + r0*512 + kg));
            aF[ks][1] = tf32c(__ldg(jb.whh + r1*512 + kg));
            aF[ks][2] = tf32c(__ldg(jb.whh + r0*512 + kg + 4));
            aF[ks][3] = tf32c(__ldg(jb.whh + r1*512 + kg + 4));
        }
    }

    // finalize mapping (coalesced): item = b*16 + col
    const int col0 = tid & 15,          b0i = tid >> 4;           // items 0..383
    const int col1 = (tid + 384) & 15,  b1i = (tid + 384) >> 4;   // items 384..511
    const bool has1 = (tid < 128);
    float hp0 = 0.f, hp1 = 0.f;

    for (int s = 0; s < jb.T; s++) {
        const int t = jb.dir ? (jb.T - 1 - s) : s;

        // gi prefetch — h-independent, overlaps exchange latency
        long long gb0 = ((long long)(t*32 + b0i))*GG + c*16 + col0;
        float giR0 = __ldg(jb.gi + gb0);
        float giZ0 = __ldg(jb.gi + gb0 + 512);
        float giN0 = __ldg(jb.gi + gb0 + 1024);
        float giR1 = 0.f, giZ1 = 0.f, giN1 = 0.f;
        if (has1) {
            long long gb1 = ((long long)(t*32 + b1i))*GG + c*16 + col1;
            giR1 = __ldg(jb.gi + gb1);
            giZ1 = __ldg(jb.gi + gb1 + 512);
            giN1 = __ldg(jb.gi + gb1 + 1024);
        }

        if (s == 0) {
            for (int b = m; b < 32; b += 3)
                *(uint4*)&hbits[b*HSW + kq*128 + lane*4] = make_uint4(0u,0u,0u,0u);
        } else {
            const unsigned tag = ((unsigned)(s - 1) & 127u) + 1u;   // producer step s-1
            const unsigned* src = stg + ((s-1)&1)*(B*HH) + kq*128;
            // phase 1: issue ALL loads back-to-back (MLP ~11)
            uint4 v[11];
#pragma unroll
            for (int i = 0; i < 11; i++) {
                int b = m + 3*i;
                if (b < 32) v[i] = ldcg4(src + b*512 + lane*4);
            }
            // phase 2: verify tags; retry only stragglers; mask+store to SMEM
#pragma unroll
            for (int i = 0; i < 11; i++) {
                int b = m + 3*i;
                if (b < 32) {
                    const unsigned* p = src + b*512 + lane*4;
                    while ((((v[i].x ^ tag) | (v[i].y ^ tag) |
                             (v[i].z ^ tag) | (v[i].w ^ tag)) & 0xffu) != 0u)
                        v[i] = ldcg4(p);
                    v[i].x &= TF32MASK; v[i].y &= TF32MASK;
                    v[i].z &= TF32MASK; v[i].w &= TF32MASK;
                    *(uint4*)&hbits[b*HSW + kq*128 + lane*4] = v[i];
                }
            }
        }
        // triple barrier: the 3 warps of quarter kq (96 threads)
        asm volatile("bar.sync %0, %1;" :: "r"(kq + 1), "r"(96) : "memory");

        // tensor GEMM: C[48 x 32] partial over this warp's k-quarter
        float acc[4][4];
#pragma unroll
        for (int nt = 0; nt < 4; nt++)
#pragma unroll
            for (int q = 0; q < 4; q++) acc[nt][q] = 0.f;
#pragma unroll
        for (int ks = 0; ks < 16; ks++) {
            const int kg = kq*128 + ks*8;
#pragma unroll
            for (int nt = 0; nt < 4; nt++) {
                unsigned bfr[2];
                bfr[0] = hbits[(nt*8 + lr)*HSW + kg + lc];
                bfr[1] = hbits[(nt*8 + lr)*HSW + kg + lc + 4];
                mma_tf32(acc[nt], aF[ks], bfr);
            }
        }
        {
            float* rp = red + kq*48*RB;
#pragma unroll
            for (int nt = 0; nt < 4; nt++) {
                int gr = m*16 + lr, bc = nt*8 + 2*lc;
                rp[gr*RB + bc]       = acc[nt][0];
                rp[gr*RB + bc + 1]   = acc[nt][1];
                rp[(gr+8)*RB + bc]   = acc[nt][2];
                rp[(gr+8)*RB + bc+1] = acc[nt][3];
            }
        }
        __syncthreads();   // all red writes visible before finalize reads

        // finalize gates; stage tagged tf32 h (critical path), then fp32 out[]
        unsigned* dstS = stg + (s&1)*(B*HH);
        const unsigned tagN = ((unsigned)s & 127u) + 1u;   // tag for step s
        float hn0, hn1 = 0.f;
        {
            float gr=0, gz=0, gn=0;
#pragma unroll
            for (int q = 0; q < 4; q++) {
                const float* rp = red + q*48*RB;
                gr += rp[col0*RB + b0i];
                gz += rp[(16+col0)*RB + b0i];
                gn += rp[(32+col0)*RB + b0i];
            }
            float r = 1.f/(1.f + __expf(-(giR0 + gr + bhh_s[col0])));
            float z = 1.f/(1.f + __expf(-(giZ0 + gz + bhh_s[16+col0])));
            float n = fast_tanh(giN0 + r*(gn + bhh_s[32+col0]));
            hn0 = (1.f - z)*n + z*hp0;
            hp0 = hn0;
            stcg(dstS + b0i*512 + c*16 + col0, tf32c(hn0) | tagN);
        }
        if (has1) {
            float gr=0, gz=0, gn=0;
#pragma unroll
            for (int q = 0; q < 4; q++) {
                const float* rp = red + q*48*RB;
                gr += rp[col1*RB + b1i];
                gz += rp[(16+col1)*RB + b1i];
                gn += rp[(32+col1)*RB + b1i];
            }
            float r = 1.f/(1.f + __expf(-(giR1 + gr + bhh_s[col1])));
            float z = 1.f/(1.f + __expf(-(giZ1 + gz + bhh_s[16+col1])));
            float n = fast_tanh(giN1 + r*(gn + bhh_s[32+col1]));
            hn1 = (1.f - z)*n + z*hp1;
            hp1 = hn1;
            stcg(dstS + b1i*512 + c*16 + col1, tf32c(hn1) | tagN);
        }

        // off-critical-path fp32 outputs
        jb.out[((long long)(t*32 + b0i))*D2 + jb.dOff + c*16 + col0] = hn0;
        if (has1)
            jb.out[((long long)(t*32 + b1i))*D2 + jb.dOff + c*16 + col1] = hn1;

        __syncthreads();   // protect red/hbits from next-iteration overwrites
    }
}

// ---- attention (seq rows interleaved: row = t*B + b) ----
__global__ __launch_bounds__(256) void attn_kernel(
    const float* __restrict__ lastbuf, int lastt,
    const float* __restrict__ seqbuf, int T,
    const float* __restrict__ i_audio, int mode, float* __restrict__ Hout)
{
    __shared__ float alast[1024];
    __shared__ float sc[512];
    __shared__ float pros_s[64];
    __shared__ float p2s;
    __shared__ float redsm[8];
    const int b = blockIdx.x, tid = threadIdx.x;
    const int w = tid >> 5, lane = tid & 31;

    for (int d = tid; d < 1024; d += 256)
        alast[d] = lastbuf[((long long)(lastt*B + b))*D2 + d];
    if (tid < 64) pros_s[tid] = i_audio[((long long)(b*AUD_T + TA))*NMFCC + tid];
    __syncthreads();
    if (tid < 32) {
        float v = 0.f;
        for (int j = tid; j < 64; j += 32) v += pros_s[j]*pros_s[j];
#pragma unroll
        for (int o = 16; o; o >>= 1) v += __shfl_down_sync(0xffffffffu, v, o);
        if (tid == 0) p2s = v;
    }
    __syncthreads();
    for (int t = w; t < T; t += 8) {
        const float* row = seqbuf + ((long long)(t*B + b))*D2;
        float v = 0.f;
        for (int d = lane; d < 1024; d += 32) v += alast[d] * row[d];
#pragma unroll
        for (int o = 16; o; o >>= 1) v += __shfl_down_sync(0xffffffffu, v, o);
        if (lane == 0) sc[t] = v + p2s;
    }
    __syncthreads();
    float ps = 0.f;
    for (int t = tid; t < T; t += 256) ps += sc[t];
#pragma unroll
    for (int o = 16; o; o >>= 1) ps += __shfl_down_sync(0xffffffffu, ps, o);
    if (lane == 0) redsm[w] = ps;
    __syncthreads();
    if (tid == 0) { float S=0.f; for (int i=0;i<8;i++) S += redsm[i]; redsm[0]=S; }
    __syncthreads();
    float S = redsm[0];
    float denom = (mode == 1) ? S : (1.f + S);
    float sumA  = (mode == 1) ? 1.f : ((float)T + S) / denom;
    __syncthreads();
    for (int t = tid; t < T; t += 256)
        sc[t] = ((mode == 1) ? sc[t] : (1.f + sc[t])) / denom;
    __syncthreads();
    float acc[4] = {0.f,0.f,0.f,0.f};
    for (int t = 0; t < T; t++) {
        float a = sc[t];
        const float* row = seqbuf + ((long long)(t*B + b))*D2;
#pragma unroll
        for (int q = 0; q < 4; q++) acc[q] += a * row[tid + q*256];
    }
#pragma unroll
    for (int q = 0; q < 4; q++) Hout[b*1088 + tid + q*256] = acc[q];
    if (tid < 64) Hout[b*1088 + 1024 + tid] = sumA * pros_s[tid];
}

__global__ void final_kernel(const float* __restrict__ fc_w, const float* __restrict__ fc_b,
                             const float* __restrict__ H1, const float* __restrict__ H2,
                             float* __restrict__ out)
{
    const int b = blockIdx.x;
    const int w = threadIdx.x >> 5, lane = threadIdx.x & 31;
    __shared__ float lg[NCLS];
    if (w < NCLS) {
        const float* wr = fc_w + w * 2176;
        float acc = 0.f;
        for (int i = lane; i < 1088; i += 32) acc += H1[b*1088 + i] * wr[i];
        for (int i = lane; i < 1088; i += 32) acc += H2[b*1088 + i] * wr[1088 + i];
#pragma unroll
        for (int o = 16; o; o >>= 1) acc += __shfl_down_sync(0xffffffffu, acc, o);
        if (lane == 0) lg[w] = acc + fc_b[w];
    }
    __syncthreads();
    if (threadIdx.x == 0) {
        float m = lg[0];
        for (int c = 1; c < NCLS; c++) m = fmaxf(m, lg[c]);
        float e[NCLS], s = 0.f;
        for (int c = 0; c < NCLS; c++) { e[c] = expf(lg[c] - m); s += e[c]; }
        for (int c = 0; c < NCLS; c++) out[b*NCLS + c] = e[c] / s;
    }
}

extern "C" void kernel_launch(void* const* d_in, const int* in_sizes, int n_in,
                              void* d_out, int out_size)
{
    const float* i_audio = (const float*)d_in[0];
    const int*   i_text  = (const int*)  d_in[1];
    const float* emb     = (const float*)d_in[2];
    const float* fc_w    = (const float*)d_in[3];
    const float* fc_b    = (const float*)d_in[4];
    const float* aWih0   = (const float*)d_in[5];
    const float* aWhh0   = (const float*)d_in[6];
    const float* ab0     = (const float*)d_in[7];
    const float* aWih1   = (const float*)d_in[8];
    const float* aWhh1   = (const float*)d_in[9];
    const float* ab1     = (const float*)d_in[10];
    const float* tWih0   = (const float*)d_in[11];
    const float* tWhh0   = (const float*)d_in[12];
    const float* tb0     = (const float*)d_in[13];
    const float* tWih1   = (const float*)d_in[14];
    const float* tWhh1   = (const float*)d_in[15];
    const float* tb1     = (const float*)d_in[16];
    float* out = (float*)d_out;

    float *gi_a, *gi_t, *xt, *oa0, *oa1, *ot0, *ot1, *h1, *h2;
    cudaGetSymbolAddress((void**)&gi_a, g_gi_a);
    cudaGetSymbolAddress((void**)&gi_t, g_gi_t);
    cudaGetSymbolAddress((void**)&xt,   g_x_text);
    cudaGetSymbolAddress((void**)&oa0,  g_out_a0);
    cudaGetSymbolAddress((void**)&oa1,  g_out_a1);
    cudaGetSymbolAddress((void**)&ot0,  g_out_t0);
    cudaGetSymbolAddress((void**)&ot1,  g_out_t1);
    cudaGetSymbolAddress((void**)&h1,   g_H1);
    cudaGetSymbolAddress((void**)&h2,   g_H2);

    cudaFuncSetAttribute(scan_kernel, cudaFuncAttributeMaxDynamicSharedMemorySize, SCAN_SMEM);

    const long long SLA = (long long)B*TA*GG;
    const long long SLT = (long long)B*TT*GG;
    const int WHH = GG*HH;

    init_kernel<<<(B*TT*NEMB + 255)/256, 256>>>(i_text, emb);

    GJobs g0;
    g0.j[0] = { i_audio, aWih0,          ab0,      gi_a,     NMFCC, TA, (long long)AUD_T*NMFCC, NMFCC };
    g0.j[1] = { i_audio, aWih0+GG*NMFCC, ab0+2*GG, gi_a+SLA, NMFCC, TA, (long long)AUD_T*NMFCC, NMFCC };
    g0.j[2] = { xt,      tWih0,          tb0,      gi_t,     NEMB,  TT, (long long)TT*NEMB,    NEMB };
    g0.j[3] = { xt,      tWih0+GG*NEMB,  tb0+2*GG, gi_t+SLT, NEMB,  TT, (long long)TT*NEMB,    NEMB };
    g0.yoff[0]=0; g0.yoff[1]=128; g0.yoff[2]=256; g0.yoff[3]=288; g0.yoff[4]=320;
    tgemm<<<dim3(GG/128, 320), 256>>>(g0);

    ScanArgs s0;
    s0.job[0] = { gi_a,     aWhh0,     ab0+GG,   oa0, TA, 0, 0,   0 };
    s0.job[1] = { gi_a+SLA, aWhh0+WHH, ab0+3*GG, oa0, TA, 1, 512, 1 };
    s0.job[2] = { gi_t,     tWhh0,     tb0+GG,   ot0, TT, 0, 0,   2 };
    s0.job[3] = { gi_t+SLT, tWhh0+WHH, tb0+3*GG, ot0, TT, 1, 512, 3 };
    scan_kernel<<<128, 384, SCAN_SMEM>>>(s0);

    GJobs g1;
    g1.j[0] = { oa0, aWih1,       ab1,      gi_a,     D2, TA, (long long)D2, (long long)B*D2 };
    g1.j[1] = { oa0, aWih1+GG*D2, ab1+2*GG, gi_a+SLA, D2, TA, (long long)D2, (long long)B*D2 };
    g1.j[2] = { ot0, tWih1,       tb1,      gi_t,     D2, TT, (long long)D2, (long long)B*D2 };
    g1.j[3] = { ot0, tWih1+GG*D2, tb1+2*GG, gi_t+SLT, D2, TT, (long long)D2, (long long)B*D2 };
    g1.yoff[0]=0; g1.yoff[1]=128; g1.yoff[2]=256; g1.yoff[3]=288; g1.yoff[4]=320;
    tgemm<<<dim3(GG/128, 320), 256>>>(g1);

    ScanArgs s1;
    s1.job[0] = { gi_a,     aWhh1,     ab1+GG,   oa1, TA, 0, 0,   4 };
    s1.job[1] = { gi_a+SLA, aWhh1+WHH, ab1+3*GG, oa1, TA, 1, 512, 5 };
    s1.job[2] = { gi_t,     tWhh1,     tb1+GG,   ot1, TT, 0, 0,   6 };
    s1.job[3] = { gi_t+SLT, tWhh1+WHH, tb1+3*GG, ot1, TT, 1, 512, 7 };
    scan_kernel<<<128, 384, SCAN_SMEM>>>(s1);

    attn_kernel<<<B, 256>>>(oa1, TA-1, ot1, TT, i_audio, 1, h1);
    attn_kernel<<<B, 256>>>(ot1, TT-1, oa1, TA, i_audio, 2, h2);
    final_kernel<<<B, 256>>>(fc_w, fc_b, h1, h2, out);
}

// round 13
// speedup vs baseline: 1.4183x; 1.0685x over previous
#include <cuda_runtime.h>
#include <cuda_bf16.h>
#include <math.h>

#define B      32
#define TA     512
#define TT     128
#define HH     512
#define GG     1536
#define D2     1024
#define NMFCC  80
#define NEMB   300
#define AUD_T  513
#define NCLS   7

// ---- device scratch ----
// gi and GRU outputs are TIME-MAJOR, BATCH-INTERLEAVED: row index = t*B + b.
__device__ float g_x_text[B*TT*NEMB];
__device__ float g_gi_a[2u*B*TA*GG];
__device__ float g_gi_t[2u*B*TT*GG];
__device__ float g_out_a0[B*TA*D2];
__device__ float g_out_a1[B*TA*D2];
__device__ float g_out_t0[B*TT*D2];
__device__ float g_out_t1[B*TT*D2];
__device__ float g_H1[B*1088];
__device__ float g_H2[B*1088];
// staged h: per group, double-buffered; word = tf32bits (top 19) | tag13 (low bits)
#define STG_GRP (2*B*HH)
__device__ unsigned g_stage[8*STG_GRP];

__device__ __forceinline__ unsigned tf32c(float x) {
    unsigned u; asm("cvt.rna.tf32.f32 %0, %1;" : "=r"(u) : "f"(x)); return u;
}
__device__ __forceinline__ float fast_tanh(float x) {
    float y; asm("tanh.approx.f32 %0, %1;" : "=f"(y) : "f"(x)); return y;
}
__device__ __forceinline__ void mma_tf32(float* c, const unsigned* a, const unsigned* b) {
    asm("mma.sync.aligned.m16n8k8.row.col.f32.tf32.tf32.f32 "
        "{%0,%1,%2,%3},{%4,%5,%6,%7},{%8,%9},{%0,%1,%2,%3};"
        : "+f"(c[0]), "+f"(c[1]), "+f"(c[2]), "+f"(c[3])
        : "r"(a[0]), "r"(a[1]), "r"(a[2]), "r"(a[3]), "r"(b[0]), "r"(b[1]));
}
__device__ __forceinline__ uint4 ldcg4(const unsigned* p) {
    uint4 v;
    asm volatile("ld.global.cg.v4.u32 {%0,%1,%2,%3}, [%4];"
                 : "=r"(v.x), "=r"(v.y), "=r"(v.z), "=r"(v.w) : "l"(p) : "memory");
    return v;
}
__device__ __forceinline__ void stcg(unsigned* p, unsigned v) {
    asm volatile("st.global.cg.u32 [%0], %1;" :: "l"(p), "r"(v) : "memory");
}

// fused: staging clear (removes stale tags across graph replays) + text embedding
__global__ void init_kernel(const int* __restrict__ itext, const float* __restrict__ emb) {
    int i = blockIdx.x * blockDim.x + threadIdx.x;
    if (i < 8*STG_GRP) g_stage[i] = 0u;
    if (i < B*TT*NEMB) {
        int e = i % NEMB, bt = i / NEMB;
        g_x_text[i] = emb[(long long)itext[bt] * NEMB + e];
    }
}

// ---- fused tf32 tensor-core GEMM: 4 jobs in one launch ----
struct GJob { const float* X; const float* W; const float* bias; float* C;
              int K; int rows_per_b; long long bstride; long long xrstride; };
struct GJobs { GJob j[4]; int yoff[5]; };

__global__ __launch_bounds__(256) void tgemm(GJobs js)
{
    __shared__ unsigned Xs[32][136];
    __shared__ unsigned Ws[32][136];
    const int tid = threadIdx.x;
    const int lane = tid & 31, wid = tid >> 5;
    const int warpM = wid & 3, warpN = wid >> 2;
    const int lr = lane >> 2, lc = lane & 3;

    int jj = 0;
#pragma unroll
    for (int q = 1; q < 4; q++) if ((int)blockIdx.y >= js.yoff[q]) jj = q;
    const GJob jb = js.j[jj];
    const int K = jb.K;
    const int m_base = (blockIdx.y - js.yoff[jj]) * 128;
    const int n_base = blockIdx.x * 128;

    float acc[2][8][4];
#pragma unroll
    for (int mt = 0; mt < 2; mt++)
#pragma unroll
        for (int nt = 0; nt < 8; nt++)
#pragma unroll
            for (int q = 0; q < 4; q++) acc[mt][nt][q] = 0.f;

    const int row = tid >> 1;
    const int f4b = (tid & 1) * 4;
    const int mg = m_base + row;
    const int bb = mg / jb.rows_per_b, rr = mg - bb * jb.rows_per_b;
    const float* xrow = jb.X + (long long)bb * jb.bstride + (long long)rr * jb.xrstride;
    const float* wrow = jb.W + (long long)(n_base + row) * K;

    for (int k0 = 0; k0 < K; k0 += 32) {
#pragma unroll
        for (int q = 0; q < 4; q++) {
            int ks = (f4b + q) * 4;
            int kk = k0 + ks;
            float4 xv = make_float4(0.f,0.f,0.f,0.f), wv = xv;
            if (kk + 4 <= K) { xv = *(const float4*)(xrow + kk); wv = *(const float4*)(wrow + kk); }
            Xs[ks+0][row]=tf32c(xv.x); Xs[ks+1][row]=tf32c(xv.y);
            Xs[ks+2][row]=tf32c(xv.z); Xs[ks+3][row]=tf32c(xv.w);
            Ws[ks+0][row]=tf32c(wv.x); Ws[ks+1][row]=tf32c(wv.y);
            Ws[ks+2][row]=tf32c(wv.z); Ws[ks+3][row]=tf32c(wv.w);
        }
        __syncthreads();
#pragma unroll
        for (int kk = 0; kk < 4; kk++) {
            const int kb = kk * 8;
            unsigned a[2][4], b[8][2];
#pragma unroll
            for (int mt = 0; mt < 2; mt++) {
                int mr = warpM*32 + mt*16;
                a[mt][0] = Xs[kb+lc][mr + lr];
                a[mt][1] = Xs[kb+lc][mr + 8 + lr];
                a[mt][2] = Xs[kb+4+lc][mr + lr];
                a[mt][3] = Xs[kb+4+lc][mr + 8 + lr];
            }
#pragma unroll
            for (int nt = 0; nt < 8; nt++) {
                int nc = warpN*64 + nt*8;
                b[nt][0] = Ws[kb+lc][nc + lr];
                b[nt][1] = Ws[kb+4+lc][nc + lr];
            }
#pragma unroll
            for (int mt = 0; mt < 2; mt++)
#pragma unroll
                for (int nt = 0; nt < 8; nt++) mma_tf32(acc[mt][nt], a[mt], b[nt]);
        }
        __syncthreads();
    }
#pragma unroll
    for (int mt = 0; mt < 2; mt++) {
#pragma unroll
        for (int half = 0; half < 2; half++) {
            int mr = m_base + warpM*32 + mt*16 + lr + half*8;
            int bbo = mr / jb.rows_per_b, rro = mr - bbo * jb.rows_per_b;
            long long crow = (long long)rro * 32 + bbo;    // interleaved row t*32+b
#pragma unroll
            for (int nt = 0; nt < 8; nt++) {
                int nc = n_base + warpN*64 + nt*8 + 2*lc;
                float2 v;
                v.x = acc[mt][nt][half*2+0] + jb.bias[nc];
                v.y = acc[mt][nt][half*2+1] + jb.bias[nc+1];
                *(float2*)(jb.C + crow * GG + nc) = v;
            }
        }
    }
}

// ---- persistent tf32 GRU scan: 4 groups x 32 CTAs, CTA owns 16 h-cols ----
// 12 warps: warp = (m in {r,z,n}, kq in 0..3).
// h exchange: SELF-VALIDATING tagged words (tf32bits | tag13, never wraps) with
// BATCHED retry passes: check all tags, reissue ALL failed loads as one MLP
// wave, re-check — one L2 round trip per pass instead of one per item.
struct ScanJob { const float* gi; const float* whh; const float* bhh; float* out;
                 int T; int dir; int dOff; int ctr; };
struct ScanArgs { ScanJob job[4]; };

#define HSW 516
#define RB  33
#define SCAN_SMEM ((32*HSW + 4*48*RB) * 4)
#define TF32MASK 0xffffe000u
#define TAGMASK  0x00001fffu

__global__ __launch_bounds__(384, 1) void scan_kernel(ScanArgs args)
{
    const int group = blockIdx.x >> 5, c = blockIdx.x & 31;
    const ScanJob jb = args.job[group];
    unsigned* stg = g_stage + jb.ctr * STG_GRP;

    extern __shared__ unsigned smu[];
    unsigned* hbits = smu;                       // 32 x 516 (tf32 h)
    float* red = (float*)(smu + 32*HSW);         // 4 x 48 x 33
    __shared__ float bhh_s[48];

    const int tid  = threadIdx.x;
    const int lane = tid & 31, wid = tid >> 5;
    const int m = wid % 3, kq = wid / 3;         // gate tile, k-quarter
    const int lr = lane >> 2, lc = lane & 3;

    if (tid < 48) {
        int gl = tid;
        int grow = (gl < 16) ? (c*16 + gl) : (gl < 32) ? (512 + c*16 + gl - 16) : (1024 + c*16 + gl - 32);
        bhh_s[gl] = jb.bhh[grow];
    }
    __syncthreads();

    // preload Whh fragments (static for whole scan)
    unsigned aF[16][4];
    {
        const int r0 = m*512 + c*16 + lr;
        const int r1 = r0 + 8;
#pragma unroll
        for (int ks = 0; ks < 16; ks++) {
            int kg = kq*128 + ks*8 + lc;
            aF[ks][0] = tf32c(__ldg(jb.whh + r0*512 + kg));
            aF[ks][1] = tf32c(__ldg(jb.whh + r1*512 + kg));
            aF[ks][2] = tf32c(__ldg(jb.whh + r0*512 + kg + 4));
            aF[ks][3] = tf32c(__ldg(jb.whh + r1*512 + kg + 4));
        }
    }

    // finalize mapping (coalesced): item = b*16 + col
    const int col0 = tid & 15,          b0i = tid >> 4;           // items 0..383
    const int col1 = (tid + 384) & 15,  b1i = (tid + 384) >> 4;   // items 384..511
    const bool has1 = (tid < 128);
    float hp0 = 0.f, hp1 = 0.f;

    for (int s = 0; s < jb.T; s++) {
        const int t = jb.dir ? (jb.T - 1 - s) : s;

        // gi prefetch — h-independent, overlaps exchange latency
        long long gb0 = ((long long)(t*32 + b0i))*GG + c*16 + col0;
        float giR0 = __ldg(jb.gi + gb0);
        float giZ0 = __ldg(jb.gi + gb0 + 512);
        float giN0 = __ldg(jb.gi + gb0 + 1024);
        float giR1 = 0.f, giZ1 = 0.f, giN1 = 0.f;
        if (has1) {
            long long gb1 = ((long long)(t*32 + b1i))*GG + c*16 + col1;
            giR1 = __ldg(jb.gi + gb1);
            giZ1 = __ldg(jb.gi + gb1 + 512);
            giN1 = __ldg(jb.gi + gb1 + 1024);
        }

        if (s == 0) {
            for (int b = m; b < 32; b += 3)
                *(uint4*)&hbits[b*HSW + kq*128 + lane*4] = make_uint4(0u,0u,0u,0u);
        } else {
            const unsigned tag = (unsigned)s;    // producer step s-1 wrote tag s
            const unsigned* src = stg + ((s-1)&1)*(B*HH) + kq*128;
            // phase 1: issue ALL loads back-to-back (MLP ~11)
            uint4 v[11];
#pragma unroll
            for (int i = 0; i < 11; i++) {
                int b = m + 3*i;
                if (b < 32) v[i] = ldcg4(src + b*512 + lane*4);
            }
            // phase 2: batched passes — check tags, reissue failures as one wave
            unsigned pend = (m == 2) ? 0x3ffu : 0x7ffu;   // valid-item bitmask
            for (;;) {
                unsigned np = 0u;
#pragma unroll
                for (int i = 0; i < 11; i++) {
                    if (pend & (1u << i)) {
                        if ((((v[i].x ^ tag) | (v[i].y ^ tag) |
                              (v[i].z ^ tag) | (v[i].w ^ tag)) & TAGMASK) != 0u)
                            np |= (1u << i);
                    }
                }
                pend = np;
                if (pend == 0u) break;
#pragma unroll
                for (int i = 0; i < 11; i++)
                    if (pend & (1u << i))
                        v[i] = ldcg4(src + (m + 3*i)*512 + lane*4);
            }
            // mask tags off, store to SMEM
#pragma unroll
            for (int i = 0; i < 11; i++) {
                int b = m + 3*i;
                if (b < 32) {
                    v[i].x &= TF32MASK; v[i].y &= TF32MASK;
                    v[i].z &= TF32MASK; v[i].w &= TF32MASK;
                    *(uint4*)&hbits[b*HSW + kq*128 + lane*4] = v[i];
                }
            }
        }
        // triple barrier: the 3 warps of quarter kq (96 threads)
        asm volatile("bar.sync %0, %1;" :: "r"(kq + 1), "r"(96) : "memory");

        // tensor GEMM: C[48 x 32] partial over this warp's k-quarter
        float acc[4][4];
#pragma unroll
        for (int nt = 0; nt < 4; nt++)
#pragma unroll
            for (int q = 0; q < 4; q++) acc[nt][q] = 0.f;
#pragma unroll
        for (int ks = 0; ks < 16; ks++) {
            const int kg = kq*128 + ks*8;
#pragma unroll
            for (int nt = 0; nt < 4; nt++) {
                unsigned bfr[2];
                bfr[0] = hbits[(nt*8 + lr)*HSW + kg + lc];
                bfr[1] = hbits[(nt*8 + lr)*HSW + kg + lc + 4];
                mma_tf32(acc[nt], aF[ks], bfr);
            }
        }
        {
            float* rp = red + kq*48*RB;
#pragma unroll
            for (int nt = 0; nt < 4; nt++) {
                int gr = m*16 + lr, bc = nt*8 + 2*lc;
                rp[gr*RB + bc]       = acc[nt][0];
                rp[gr*RB + bc + 1]   = acc[nt][1];
                rp[(gr+8)*RB + bc]   = acc[nt][2];
                rp[(gr+8)*RB + bc+1] = acc[nt][3];
            }
        }
        __syncthreads();   // all red writes visible before finalize reads

        // finalize gates; stage tagged tf32 h (critical path), then fp32 out[]
        unsigned* dstS = stg + (s&1)*(B*HH);
        const unsigned tagN = (unsigned)(s + 1);   // tag for step s (<= 512, 13 bits)
        float hn0, hn1 = 0.f;
        {
            float gr=0, gz=0, gn=0;
#pragma unroll
            for (int q = 0; q < 4; q++) {
                const float* rp = red + q*48*RB;
                gr += rp[col0*RB + b0i];
                gz += rp[(16+col0)*RB + b0i];
                gn += rp[(32+col0)*RB + b0i];
            }
            float r = 1.f/(1.f + __expf(-(giR0 + gr + bhh_s[col0])));
            float z = 1.f/(1.f + __expf(-(giZ0 + gz + bhh_s[16+col0])));
            float n = fast_tanh(giN0 + r*(gn + bhh_s[32+col0]));
            hn0 = (1.f - z)*n + z*hp0;
            hp0 = hn0;
            stcg(dstS + b0i*512 + c*16 + col0, tf32c(hn0) | tagN);
        }
        if (has1) {
            float gr=0, gz=0, gn=0;
#pragma unroll
            for (int q = 0; q < 4; q++) {
                const float* rp = red + q*48*RB;
                gr += rp[col1*RB + b1i];
                gz += rp[(16+col1)*RB + b1i];
                gn += rp[(32+col1)*RB + b1i];
            }
            float r = 1.f/(1.f + __expf(-(giR1 + gr + bhh_s[col1])));
            float z = 1.f/(1.f + __expf(-(giZ1 + gz + bhh_s[16+col1])));
            float n = fast_tanh(giN1 + r*(gn + bhh_s[32+col1]));
            hn1 = (1.f - z)*n + z*hp1;
            hp1 = hn1;
            stcg(dstS + b1i*512 + c*16 + col1, tf32c(hn1) | tagN);
        }

        // off-critical-path fp32 outputs
        jb.out[((long long)(t*32 + b0i))*D2 + jb.dOff + c*16 + col0] = hn0;
        if (has1)
            jb.out[((long long)(t*32 + b1i))*D2 + jb.dOff + c*16 + col1] = hn1;

        __syncthreads();   // protect red/hbits from next-iteration overwrites
    }
}

// ---- attention (seq rows interleaved: row = t*B + b) ----
__global__ __launch_bounds__(256) void attn_kernel(
    const float* __restrict__ lastbuf, int lastt,
    const float* __restrict__ seqbuf, int T,
    const float* __restrict__ i_audio, int mode, float* __restrict__ Hout)
{
    __shared__ float alast[1024];
    __shared__ float sc[512];
    __shared__ float pros_s[64];
    __shared__ float p2s;
    __shared__ float redsm[8];
    const int b = blockIdx.x, tid = threadIdx.x;
    const int w = tid >> 5, lane = tid & 31;

    for (int d = tid; d < 1024; d += 256)
        alast[d] = lastbuf[((long long)(lastt*B + b))*D2 + d];
    if (tid < 64) pros_s[tid] = i_audio[((long long)(b*AUD_T + TA))*NMFCC + tid];
    __syncthreads();
    if (tid < 32) {
        float v = 0.f;
        for (int j = tid; j < 64; j += 32) v += pros_s[j]*pros_s[j];
#pragma unroll
        for (int o = 16; o; o >>= 1) v += __shfl_down_sync(0xffffffffu, v, o);
        if (tid == 0) p2s = v;
    }
    __syncthreads();
    for (int t = w; t < T; t += 8) {
        const float* row = seqbuf + ((long long)(t*B + b))*D2;
        float v = 0.f;
        for (int d = lane; d < 1024; d += 32) v += alast[d] * row[d];
#pragma unroll
        for (int o = 16; o; o >>= 1) v += __shfl_down_sync(0xffffffffu, v, o);
        if (lane == 0) sc[t] = v + p2s;
    }
    __syncthreads();
    float ps = 0.f;
    for (int t = tid; t < T; t += 256) ps += sc[t];
#pragma unroll
    for (int o = 16; o; o >>= 1) ps += __shfl_down_sync(0xffffffffu, ps, o);
    if (lane == 0) redsm[w] = ps;
    __syncthreads();
    if (tid == 0) { float S=0.f; for (int i=0;i<8;i++) S += redsm[i]; redsm[0]=S; }
    __syncthreads();
    float S = redsm[0];
    float denom = (mode == 1) ? S : (1.f + S);
    float sumA  = (mode == 1) ? 1.f : ((float)T + S) / denom;
    __syncthreads();
    for (int t = tid; t < T; t += 256)
        sc[t] = ((mode == 1) ? sc[t] : (1.f + sc[t])) / denom;
    __syncthreads();
    float acc[4] = {0.f,0.f,0.f,0.f};
    for (int t = 0; t < T; t++) {
        float a = sc[t];
        const float* row = seqbuf + ((long long)(t*B + b))*D2;
#pragma unroll
        for (int q = 0; q < 4; q++) acc[q] += a * row[tid + q*256];
    }
#pragma unroll
    for (int q = 0; q < 4; q++) Hout[b*1088 + tid + q*256] = acc[q];
    if (tid < 64) Hout[b*1088 + 1024 + tid] = sumA * pros_s[tid];
}

__global__ void final_kernel(const float* __restrict__ fc_w, const float* __restrict__ fc_b,
                             const float* __restrict__ H1, const float* __restrict__ H2,
                             float* __restrict__ out)
{
    const int b = blockIdx.x;
    const int w = threadIdx.x >> 5, lane = threadIdx.x & 31;
    __shared__ float lg[NCLS];
    if (w < NCLS) {
        const float* wr = fc_w + w * 2176;
        float acc = 0.f;
        for (int i = lane; i < 1088; i += 32) acc += H1[b*1088 + i] * wr[i];
        for (int i = lane; i < 1088; i += 32) acc += H2[b*1088 + i] * wr[1088 + i];
#pragma unroll
        for (int o = 16; o; o >>= 1) acc += __shfl_down_sync(0xffffffffu, acc, o);
        if (lane == 0) lg[w] = acc + fc_b[w];
    }
    __syncthreads();
    if (threadIdx.x == 0) {
        float m = lg[0];
        for (int c = 1; c < NCLS; c++) m = fmaxf(m, lg[c]);
        float e[NCLS], s = 0.f;
        for (int c = 0; c < NCLS; c++) { e[c] = expf(lg[c] - m); s += e[c]; }
        for (int c = 0; c < NCLS; c++) out[b*NCLS + c] = e[c] / s;
    }
}

extern "C" void kernel_launch(void* const* d_in, const int* in_sizes, int n_in,
                              void* d_out, int out_size)
{
    const float* i_audio = (const float*)d_in[0];
    const int*   i_text  = (const int*)  d_in[1];
    const float* emb     = (const float*)d_in[2];
    const float* fc_w    = (const float*)d_in[3];
    const float* fc_b    = (const float*)d_in[4];
    const float* aWih0   = (const float*)d_in[5];
    const float* aWhh0   = (const float*)d_in[6];
    const float* ab0     = (const float*)d_in[7];
    const float* aWih1   = (const float*)d_in[8];
    const float* aWhh1   = (const float*)d_in[9];
    const float* ab1     = (const float*)d_in[10];
    const float* tWih0   = (const float*)d_in[11];
    const float* tWhh0   = (const float*)d_in[12];
    const float* tb0     = (const float*)d_in[13];
    const float* tWih1   = (const float*)d_in[14];
    const float* tWhh1   = (const float*)d_in[15];
    const float* tb1     = (const float*)d_in[16];
    float* out = (float*)d_out;

    float *gi_a, *gi_t, *xt, *oa0, *oa1, *ot0, *ot1, *h1, *h2;
    cudaGetSymbolAddress((void**)&gi_a, g_gi_a);
    cudaGetSymbolAddress((void**)&gi_t, g_gi_t);
    cudaGetSymbolAddress((void**)&xt,   g_x_text);
    cudaGetSymbolAddress((void**)&oa0,  g_out_a0);
    cudaGetSymbolAddress((void**)&oa1,  g_out_a1);
    cudaGetSymbolAddress((void**)&ot0,  g_out_t0);
    cudaGetSymbolAddress((void**)&ot1,  g_out_t1);
    cudaGetSymbolAddress((void**)&h1,   g_H1);
    cudaGetSymbolAddress((void**)&h2,   g_H2);

    cudaFuncSetAttribute(scan_kernel, cudaFuncAttributeMaxDynamicSharedMemorySize, SCAN_SMEM);

    const long long SLA = (long long)B*TA*GG;
    const long long SLT = (long long)B*TT*GG;
    const int WHH = GG*HH;

    init_kernel<<<(B*TT*NEMB + 255)/256, 256>>>(i_text, emb);

    GJobs g0;
    g0.j[0] = { i_audio, aWih0,          ab0,      gi_a,     NMFCC, TA, (long long)AUD_T*NMFCC, NMFCC };
    g0.j[1] = { i_audio, aWih0+GG*NMFCC, ab0+2*GG, gi_a+SLA, NMFCC, TA, (long long)AUD_T*NMFCC, NMFCC };
    g0.j[2] = { xt,      tWih0,          tb0,      gi_t,     NEMB,  TT, (long long)TT*NEMB,    NEMB };
    g0.j[3] = { xt,      tWih0+GG*NEMB,  tb0+2*GG, gi_t+SLT, NEMB,  TT, (long long)TT*NEMB,    NEMB };
    g0.yoff[0]=0; g0.yoff[1]=128; g0.yoff[2]=256; g0.yoff[3]=288; g0.yoff[4]=320;
    tgemm<<<dim3(GG/128, 320), 256>>>(g0);

    ScanArgs s0;
    s0.job[0] = { gi_a,     aWhh0,     ab0+GG,   oa0, TA, 0, 0,   0 };
    s0.job[1] = { gi_a+SLA, aWhh0+WHH, ab0+3*GG, oa0, TA, 1, 512, 1 };
    s0.job[2] = { gi_t,     tWhh0,     tb0+GG,   ot0, TT, 0, 0,   2 };
    s0.job[3] = { gi_t+SLT, tWhh0+WHH, tb0+3*GG, ot0, TT, 1, 512, 3 };
    scan_kernel<<<128, 384, SCAN_SMEM>>>(s0);

    GJobs g1;
    g1.j[0] = { oa0, aWih1,       ab1,      gi_a,     D2, TA, (long long)D2, (long long)B*D2 };
    g1.j[1] = { oa0, aWih1+GG*D2, ab1+2*GG, gi_a+SLA, D2, TA, (long long)D2, (long long)B*D2 };
    g1.j[2] = { ot0, tWih1,       tb1,      gi_t,     D2, TT, (long long)D2, (long long)B*D2 };
    g1.j[3] = { ot0, tWih1+GG*D2, tb1+2*GG, gi_t+SLT, D2, TT, (long long)D2, (long long)B*D2 };
    g1.yoff[0]=0; g1.yoff[1]=128; g1.yoff[2]=256; g1.yoff[3]=288; g1.yoff[4]=320;
    tgemm<<<dim3(GG/128, 320), 256>>>(g1);

    ScanArgs s1;
    s1.job[0] = { gi_a,     aWhh1,     ab1+GG,   oa1, TA, 0, 0,   4 };
    s1.job[1] = { gi_a+SLA, aWhh1+WHH, ab1+3*GG, oa1, TA, 1, 512, 5 };
    s1.job[2] = { gi_t,     tWhh1,     tb1+GG,   ot1, TT, 0, 0,   6 };
    s1.job[3] = { gi_t+SLT, tWhh1+WHH, tb1+3*GG, ot1, TT, 1, 512, 7 };
    scan_kernel<<<128, 384, SCAN_SMEM>>>(s1);

    attn_kernel<<<B, 256>>>(oa1, TA-1, ot1, TT, i_audio, 1, h1);
    attn_kernel<<<B, 256>>>(ot1, TT-1, oa1, TA, i_audio, 2, h2);
    final_kernel<<<B, 256>>>(fc_w, fc_b, h1, h2, out);
}